// round 8
// baseline (speedup 1.0000x reference)
#include <cuda_runtime.h>
#include <cuda_fp16.h>
#include <cstdint>

#define MAXN 1000000
#define M 9
#define T 256
#define IDX_PER_BLOCK (T * M)   // 2304 ints = 9216 bytes, 16B-aligned per block

// Scratch (allocation-free rule: __device__ globals)
__device__ float4 d_pk[MAXN];   // {x, y, ut, ut1} fp32 — grad1 gather
__device__ float4 d_gc[MAXN];   // {x, y, half2(g0,g1), half2(g2,g3)} — grad2 single gather

// Accumulators + ticket, zeroed together by one memsetAsync.
struct Acc { double lu; double lf; unsigned int ticket; unsigned int pad; };
__device__ Acc d_acc;

__device__ __forceinline__ float pack_h2(float a, float b) {
    __half2 h = __floats2half2_rn(a, b);
    return *reinterpret_cast<float*>(&h);
}
__device__ __forceinline__ float2 unpack_h2(float bits) {
    __half2 h = *reinterpret_cast<__half2*>(&bits);
    return __half22float2(h);
}

// Block-level reduce a float, one double atomicAdd per block.
__device__ __forceinline__ void block_reduce_add(float v, double* target) {
    __shared__ float warp_sums[32];
    int lane = threadIdx.x & 31;
    int wid  = threadIdx.x >> 5;
    #pragma unroll
    for (int off = 16; off > 0; off >>= 1)
        v += __shfl_down_sync(0xFFFFFFFFu, v, off);
    if (lane == 0) warp_sums[wid] = v;
    __syncthreads();
    int nwarps = (blockDim.x + 31) >> 5;
    if (wid == 0) {
        float s = (lane < nwarps) ? warp_sums[lane] : 0.0f;
        #pragma unroll
        for (int off = 16; off > 0; off >>= 1)
            s += __shfl_down_sync(0xFFFFFFFFu, s, off);
        if (lane == 0) atomicAdd(target, (double)s);
    }
}

// Cooperative idx staging: coalesced uint4 loads -> smem; stride-9 LDS later
// is bank-conflict-free (gcd(9,32)==1).
__device__ __forceinline__ void stage_idx(const int* __restrict__ idx,
                                          int* s_idx, int n) {
    int blockBase = blockIdx.x * IDX_PER_BLOCK;
    int nint = n * M;
    for (int t = threadIdx.x; t * 4 < IDX_PER_BLOCK; t += T) {
        int gi = blockBase + t * 4;
        if (gi + 3 < nint) {
            uint4 v = ((const uint4*)idx)[(blockBase >> 2) + t];
            *reinterpret_cast<uint4*>(&s_idx[t * 4]) = v;
        } else {
            #pragma unroll
            for (int j = 0; j < 4; j++)
                if (gi + j < nint) s_idx[t * 4 + j] = idx[gi + j];
        }
    }
    __syncthreads();
}

// K1: vectorized pack (4 points/thread) + loss_u.
__global__ void __launch_bounds__(T) k_pack(const float* __restrict__ up,
                       const float* __restrict__ usol,
                       const float* __restrict__ ut,
                       const float* __restrict__ x,
                       const float* __restrict__ ut1,
                       int n) {
    int base = (blockIdx.x * T + threadIdx.x) * 4;
    float lu = 0.0f;
    if (base + 3 < n) {
        float4 xa = ((const float4*)x)[base >> 1];       // x[2b..2b+3]
        float4 xb = ((const float4*)x)[(base >> 1) + 1]; // x[2b+4..2b+7]
        float4 u  = ((const float4*)ut)[base >> 2];
        float4 u1 = ((const float4*)ut1)[base >> 2];
        float4 p  = ((const float4*)up)[base >> 2];
        float4 s  = ((const float4*)usol)[base >> 2];
        float4 o0 = make_float4(xa.x, xa.y, u.x, u1.x);
        float4 o1 = make_float4(xa.z, xa.w, u.y, u1.y);
        float4 o2 = make_float4(xb.x, xb.y, u.z, u1.z);
        float4 o3 = make_float4(xb.z, xb.w, u.w, u1.w);
        d_pk[base + 0] = o0;
        d_pk[base + 1] = o1;
        d_pk[base + 2] = o2;
        d_pk[base + 3] = o3;
        float d0 = p.x - s.x, d1 = p.y - s.y, d2 = p.z - s.z, d3 = p.w - s.w;
        lu = d0 * d0 + d1 * d1 + d2 * d2 + d3 * d3;
    } else {
        for (int j = 0; j < 4; j++) {
            int i = base + j;
            if (i < n) {
                float4 pk;
                pk.x = x[2 * i];
                pk.y = x[2 * i + 1];
                pk.z = ut[i];
                pk.w = ut1[i];
                d_pk[i] = pk;
                float d = up[i] - usol[i];
                lu += d * d;
            }
        }
    }
    block_reduce_add(lu, &d_acc.lu);
}

// K2: grad1 (ut & ut1 together); writes combined {x,y,g(half)} struct.
__global__ void __launch_bounds__(T, 8) k_grad1(const int* __restrict__ idx,
                        const float4* __restrict__ inv,
                        int n) {
    __shared__ int s_idx[IDX_PER_BLOCK];
    stage_idx(idx, s_idx, n);

    int k = blockIdx.x * T + threadIdx.x;
    if (k >= n) return;

    int nb[M];
    #pragma unroll
    for (int m = 0; m < M; m++) nb[m] = s_idx[threadIdx.x * M + m];

    float4 pk = d_pk[k];
    float sx = 0.f, sy = 0.f, s1x = 0.f, s1y = 0.f;
    #pragma unroll
    for (int m = 0; m < M; m++) {
        float4 q = __ldg(&d_pk[nb[m]]);
        float dx = q.x - pk.x;
        float dy = q.y - pk.y;
        float du = q.z - pk.z;
        float du1 = q.w - pk.w;
        sx  += du  * dx;  sy  += du  * dy;
        s1x += du1 * dx;  s1y += du1 * dy;
    }
    float4 iv = __ldg(&inv[k]);
    float g0 = sx * iv.x + sy * iv.z;
    float g1 = sx * iv.y + sy * iv.w;
    float g2 = s1x * iv.x + s1y * iv.z;
    float g3 = s1x * iv.y + s1y * iv.w;

    float4 out;
    out.x = pk.x;
    out.y = pk.y;
    out.z = pack_h2(g0, g1);
    out.w = pack_h2(g2, g3);
    d_gc[k] = out;
}

// K3: grad2 + f + loss_f; last block finalizes the scalar output.
__global__ void __launch_bounds__(T, 8) k_grad2(const int* __restrict__ idx,
                        const float4* __restrict__ inv,
                        const float* __restrict__ ut,
                        const float* __restrict__ ut1,
                        int n, float* __restrict__ out) {
    __shared__ int s_idx[IDX_PER_BLOCK];
    stage_idx(idx, s_idx, n);

    int k = blockIdx.x * T + threadIdx.x;
    float ff = 0.0f;
    if (k < n) {
        int nb[M];
        #pragma unroll
        for (int m = 0; m < M; m++) nb[m] = s_idx[threadIdx.x * M + m];

        float4 gc = d_gc[k];
        float kx = gc.x, ky = gc.y;
        float2 gkA = unpack_h2(gc.z);
        float2 gkB = unpack_h2(gc.w);

        float s00 = 0.f, s01 = 0.f, s10 = 0.f, s11 = 0.f;
        float t00 = 0.f, t01 = 0.f, t10 = 0.f, t11 = 0.f;
        #pragma unroll
        for (int m = 0; m < M; m++) {
            float4 q = __ldg(&d_gc[nb[m]]);
            float dx = q.x - kx;
            float dy = q.y - ky;
            float2 gA = unpack_h2(q.z);
            float2 gB = unpack_h2(q.w);
            float d0 = gA.x - gkA.x;
            float d1 = gA.y - gkA.y;
            float e0 = gB.x - gkB.x;
            float e1 = gB.y - gkB.y;
            s00 += d0 * dx; s01 += d0 * dy;
            s10 += d1 * dx; s11 += d1 * dy;
            t00 += e0 * dx; t01 += e0 * dy;
            t10 += e1 * dx; t11 += e1 * dy;
        }
        float4 iv = __ldg(&inv[k]);
        float u_xx  = s00 * iv.x + s01 * iv.z;
        float u_yy  = s10 * iv.y + s11 * iv.w;
        float u_xx1 = t00 * iv.x + t01 * iv.z;
        float u_yy1 = t10 * iv.y + t11 * iv.w;

        float utk  = __ldg(&ut[k]);
        float ut1k = __ldg(&ut1[k]);
        float f = ut1k - utk
                - 0.01f * ((0.01f * (u_xx + u_yy) + utk - utk * utk * utk)
                         + (0.01f * (u_xx1 + u_yy1) + ut1k - ut1k * ut1k * ut1k));
        ff = f * f;
    }
    block_reduce_add(ff, &d_acc.lf);

    // Last-block finalize (ticket zeroed by memsetAsync each launch).
    if (threadIdx.x == 0) {
        __threadfence();
        unsigned int old = atomicAdd(&d_acc.ticket, 1u);
        if (old == gridDim.x - 1) {
            out[0] = (float)(d_acc.lu + 4.0 * d_acc.lf);
        }
    }
}

extern "C" void kernel_launch(void* const* d_in, const int* in_sizes, int n_in,
                              void* d_out, int out_size) {
    const float* up   = (const float*)d_in[0];
    const float* usol = (const float*)d_in[1];
    const float* ut   = (const float*)d_in[2];
    const float* x    = (const float*)d_in[3];
    const float* ut1  = (const float*)d_in[4];
    const int*   idx  = (const int*)d_in[5];
    const float4* inv = (const float4*)d_in[6];
    int n = in_sizes[0];

    // Zero accumulators + ticket without a kernel launch.
    void* acc_ptr = nullptr;
    cudaGetSymbolAddress(&acc_ptr, d_acc);
    cudaMemsetAsync(acc_ptr, 0, sizeof(Acc));

    int B  = (n + T - 1) / T;
    int Bp = (n + 4 * T - 1) / (4 * T);

    k_pack<<<Bp, T>>>(up, usol, ut, x, ut1, n);
    k_grad1<<<B, T>>>(idx, inv, n);
    k_grad2<<<B, T>>>(idx, inv, ut, ut1, n, (float*)d_out);
}

// round 9
// speedup vs baseline: 1.1082x; 1.1082x over previous
#include <cuda_runtime.h>
#include <cuda_fp16.h>
#include <cstdint>

#define MAXN 1000000
#define M 9
#define T 256

// Scratch (allocation-free rule: __device__ globals)
__device__ float4 d_pk[MAXN];   // {x, y, ut, ut1} fp32 — grad1 gather
__device__ float4 d_gc[MAXN];   // {x, y, half2(g0,g1), half2(g2,g3)} — grad2 single gather
__device__ double d_acc[2];     // [0] = loss_u, [1] = loss_f (zeroed via memsetAsync)

__device__ __forceinline__ float pack_h2(float a, float b) {
    __half2 h = __floats2half2_rn(a, b);
    return *reinterpret_cast<float*>(&h);
}
__device__ __forceinline__ float2 unpack_h2(float bits) {
    __half2 h = *reinterpret_cast<__half2*>(&bits);
    return __half22float2(h);
}

// Block-level reduce a float, one double atomicAdd per block.
__device__ __forceinline__ void block_reduce_add(float v, double* target) {
    __shared__ float warp_sums[32];
    int lane = threadIdx.x & 31;
    int wid  = threadIdx.x >> 5;
    #pragma unroll
    for (int off = 16; off > 0; off >>= 1)
        v += __shfl_down_sync(0xFFFFFFFFu, v, off);
    if (lane == 0) warp_sums[wid] = v;
    __syncthreads();
    int nwarps = (blockDim.x + 31) >> 5;
    if (wid == 0) {
        float s = (lane < nwarps) ? warp_sums[lane] : 0.0f;
        #pragma unroll
        for (int off = 16; off > 0; off >>= 1)
            s += __shfl_down_sync(0xFFFFFFFFu, s, off);
        if (lane == 0) atomicAdd(target, (double)s);
    }
}

// K1: build pack array + loss_u (1 point/thread — latency-bound stream,
// thread-parallelism beats per-thread vectorization here; R8 evidence).
__global__ void k_pack(const float* __restrict__ up,
                       const float* __restrict__ usol,
                       const float* __restrict__ ut,
                       const float* __restrict__ x,
                       const float* __restrict__ ut1,
                       int n) {
    int i = blockIdx.x * blockDim.x + threadIdx.x;
    float lu = 0.0f;
    if (i < n) {
        float2 xy = ((const float2*)x)[i];
        float4 pk;
        pk.x = xy.x;
        pk.y = xy.y;
        pk.z = ut[i];
        pk.w = ut1[i];
        d_pk[i] = pk;
        float d = up[i] - usol[i];
        lu = d * d;
    }
    block_reduce_add(lu, &d_acc[0]);
}

// K2: grad1 for ut and ut1 simultaneously (direct idx loads — NO smem staging;
// the staging barrier measurably costs more than the idx wavefronts it saves).
__global__ void __launch_bounds__(T, 8) k_grad1(const int* __restrict__ idx,
                        const float4* __restrict__ inv,
                        int n) {
    int k = blockIdx.x * blockDim.x + threadIdx.x;
    if (k >= n) return;
    float4 pk = d_pk[k];
    float sx = 0.f, sy = 0.f, s1x = 0.f, s1y = 0.f;
    #pragma unroll
    for (int m = 0; m < M; m++) {
        int nb = __ldg(&idx[k * M + m]);
        float4 q = __ldg(&d_pk[nb]);
        float dx = q.x - pk.x;
        float dy = q.y - pk.y;
        float du = q.z - pk.z;
        float du1 = q.w - pk.w;
        sx  += du  * dx;  sy  += du  * dy;
        s1x += du1 * dx;  s1y += du1 * dy;
    }
    float4 iv = __ldg(&inv[k]);
    float g0 = sx * iv.x + sy * iv.z;
    float g1 = sx * iv.y + sy * iv.w;
    float g2 = s1x * iv.x + s1y * iv.z;
    float g3 = s1x * iv.y + s1y * iv.w;

    float4 out;
    out.x = pk.x;
    out.y = pk.y;
    out.z = pack_h2(g0, g1);
    out.w = pack_h2(g2, g3);
    d_gc[k] = out;
}

// K3: grad2 for both + f + loss_f. ONE 16B gather per neighbor.
__global__ void __launch_bounds__(T, 8) k_grad2(const int* __restrict__ idx,
                        const float4* __restrict__ inv,
                        const float* __restrict__ ut,
                        const float* __restrict__ ut1,
                        int n) {
    int k = blockIdx.x * blockDim.x + threadIdx.x;
    float ff = 0.0f;
    if (k < n) {
        float4 gc = d_gc[k];
        float kx = gc.x, ky = gc.y;
        float2 gkA = unpack_h2(gc.z);
        float2 gkB = unpack_h2(gc.w);

        float s00 = 0.f, s01 = 0.f, s10 = 0.f, s11 = 0.f;
        float t00 = 0.f, t01 = 0.f, t10 = 0.f, t11 = 0.f;
        #pragma unroll
        for (int m = 0; m < M; m++) {
            int nb = __ldg(&idx[k * M + m]);
            float4 q = __ldg(&d_gc[nb]);
            float dx = q.x - kx;
            float dy = q.y - ky;
            float2 gA = unpack_h2(q.z);
            float2 gB = unpack_h2(q.w);
            float d0 = gA.x - gkA.x;
            float d1 = gA.y - gkA.y;
            float e0 = gB.x - gkB.x;
            float e1 = gB.y - gkB.y;
            s00 += d0 * dx; s01 += d0 * dy;
            s10 += d1 * dx; s11 += d1 * dy;
            t00 += e0 * dx; t01 += e0 * dy;
            t10 += e1 * dx; t11 += e1 * dy;
        }
        float4 iv = __ldg(&inv[k]);
        float u_xx  = s00 * iv.x + s01 * iv.z;
        float u_yy  = s10 * iv.y + s11 * iv.w;
        float u_xx1 = t00 * iv.x + t01 * iv.z;
        float u_yy1 = t10 * iv.y + t11 * iv.w;

        float utk  = __ldg(&ut[k]);
        float ut1k = __ldg(&ut1[k]);
        float f = ut1k - utk
                - 0.01f * ((0.01f * (u_xx + u_yy) + utk - utk * utk * utk)
                         + (0.01f * (u_xx1 + u_yy1) + ut1k - ut1k * ut1k * ut1k));
        ff = f * f;
    }
    block_reduce_add(ff, &d_acc[1]);
}

__global__ void k_final(float* out) {
    out[0] = (float)(d_acc[0] + 4.0 * d_acc[1]);
}

extern "C" void kernel_launch(void* const* d_in, const int* in_sizes, int n_in,
                              void* d_out, int out_size) {
    const float* up   = (const float*)d_in[0];
    const float* usol = (const float*)d_in[1];
    const float* ut   = (const float*)d_in[2];
    const float* x    = (const float*)d_in[3];
    const float* ut1  = (const float*)d_in[4];
    const int*   idx  = (const int*)d_in[5];
    const float4* inv = (const float4*)d_in[6];
    int n = in_sizes[0];

    // Zero accumulators without a kernel launch (graph-capturable memset).
    void* acc_ptr = nullptr;
    cudaGetSymbolAddress(&acc_ptr, d_acc);
    cudaMemsetAsync(acc_ptr, 0, 2 * sizeof(double));

    int B = (n + T - 1) / T;

    k_pack<<<B, T>>>(up, usol, ut, x, ut1, n);
    k_grad1<<<B, T>>>(idx, inv, n);
    k_grad2<<<B, T>>>(idx, inv, ut, ut1, n);
    k_final<<<1, 1>>>((float*)d_out);
}